// round 3
// baseline (speedup 1.0000x reference)
#include <cuda_runtime.h>
#include <cstdint>
#include <math.h>

#define N_NODES 100000
#define N_EDGES 800000
#define DIM     256
#define N_MASK  10000
#define RPB     16      // masked rows per block in final kernel

// ---------------- scratch (device globals; no allocation in kernel_launch) ---
__device__ __align__(16) float g_dinv[N_NODES];
__device__ __align__(16) float g_EW1[DIM * DIM];
__device__ __align__(16) float g_agg1[(size_t)N_NODES * DIM];
__device__ __align__(16) float g_agg2[(size_t)N_NODES * DIM];

// vector reduction (fire-and-forget), sm_90+
__device__ __forceinline__ void red_add_v4(float* p, float4 v) {
    asm volatile("red.global.add.v4.f32 [%0], {%1,%2,%3,%4};"
                 :: "l"(p), "f"(v.x), "f"(v.y), "f"(v.z), "f"(v.w)
                 : "memory");
}

// ---------------- degree / norm ----------------------------------------------
__global__ void k_deg_init() {
    int i = blockIdx.x * blockDim.x + threadIdx.x;
    if (i < N_NODES) g_dinv[i] = 1.0f;          // self-loop counts once
}

__global__ void k_deg_count(const int* __restrict__ dst) {
    int e = blockIdx.x * blockDim.x + threadIdx.x;
    if (e < N_EDGES) atomicAdd(&g_dinv[dst[e]], 1.0f);
}

__global__ void k_rsqrt() {
    int i = blockIdx.x * blockDim.x + threadIdx.x;
    if (i < N_NODES) g_dinv[i] = rsqrtf(g_dinv[i]);   // deg >= 1 always
}

// ---------------- EW1 = emb @ W1  (256x256x256, trivial) ---------------------
__global__ void k_ew1(const float* __restrict__ emb, const float* __restrict__ W1) {
    __shared__ float es[DIM];
    int row = blockIdx.x, j = threadIdx.x;
    es[j] = emb[row * DIM + j];
    __syncthreads();
    float acc = 0.f;
#pragma unroll 8
    for (int k = 0; k < DIM; k++) acc += es[k] * W1[k * DIM + j];
    g_EW1[row * DIM + j] = acc;
}

// ---------------- layer 1: agg1 = b1 + self + edge terms ---------------------
// init: agg1[i] = b1 + EW1[x[i]] * dinv[i]^2   (self-loop)
__global__ void k_agg1_init(const int* __restrict__ x, const float* __restrict__ b1) {
    int idx = blockIdx.x * blockDim.x + threadIdx.x;    // one float4 lane
    if (idx >= N_NODES * 64) return;
    int node = idx >> 6, q = idx & 63;
    float di = g_dinv[node];
    float w  = di * di;
    int   xv = __ldg(x + node);
    float4 v = reinterpret_cast<const float4*>(g_EW1)[(size_t)xv * 64 + q];
    float4 b = reinterpret_cast<const float4*>(b1)[q];
    float4 o = make_float4(b.x + v.x * w, b.y + v.y * w, b.z + v.z * w, b.w + v.w * w);
    reinterpret_cast<float4*>(g_agg1)[(size_t)node * 64 + q] = o;
}

// edges: agg1[dst] += EW1[x[src]] * dinv[src]*dinv[dst]   (warp per edge)
__global__ void k_edge1(const int* __restrict__ src, const int* __restrict__ dst,
                        const int* __restrict__ x) {
    int gt = blockIdx.x * blockDim.x + threadIdx.x;
    int e  = gt >> 5;
    if (e >= N_EDGES) return;
    int lane = gt & 31;
    int s = __ldg(src + e), d = __ldg(dst + e);
    float w = g_dinv[s] * g_dinv[d];
    int xs = __ldg(x + s);
    const float4* row = reinterpret_cast<const float4*>(g_EW1) + (size_t)xs * 64;
    float* out = g_agg1 + (size_t)d * DIM;
    float4 v0 = row[lane];
    float4 v1 = row[lane + 32];
    v0.x *= w; v0.y *= w; v0.z *= w; v0.w *= w;
    v1.x *= w; v1.y *= w; v1.z *= w; v1.w *= w;
    red_add_v4(out + lane * 4, v0);
    red_add_v4(out + (lane + 32) * 4, v1);
}

// ---------------- layer 2: agg2 = segsum(relu(agg1)[src]*norm)  (b2 deferred)
__global__ void k_agg2_init() {
    int idx = blockIdx.x * blockDim.x + threadIdx.x;
    if (idx >= N_NODES * 64) return;
    int node = idx >> 6, q = idx & 63;
    float di = g_dinv[node];
    float w  = di * di;
    float4 v = reinterpret_cast<const float4*>(g_agg1)[(size_t)node * 64 + q];
    float4 o = make_float4(fmaxf(v.x, 0.f) * w, fmaxf(v.y, 0.f) * w,
                           fmaxf(v.z, 0.f) * w, fmaxf(v.w, 0.f) * w);
    reinterpret_cast<float4*>(g_agg2)[(size_t)node * 64 + q] = o;
}

__global__ void k_edge2(const int* __restrict__ src, const int* __restrict__ dst) {
    int gt = blockIdx.x * blockDim.x + threadIdx.x;
    int e  = gt >> 5;
    if (e >= N_EDGES) return;
    int lane = gt & 31;
    int s = __ldg(src + e), d = __ldg(dst + e);
    float w = g_dinv[s] * g_dinv[d];
    const float4* row = reinterpret_cast<const float4*>(g_agg1) + (size_t)s * 64;
    float* out = g_agg2 + (size_t)d * DIM;
    float4 v0 = row[lane];
    float4 v1 = row[lane + 32];
    v0 = make_float4(fmaxf(v0.x, 0.f) * w, fmaxf(v0.y, 0.f) * w,
                     fmaxf(v0.z, 0.f) * w, fmaxf(v0.w, 0.f) * w);
    v1 = make_float4(fmaxf(v1.x, 0.f) * w, fmaxf(v1.y, 0.f) * w,
                     fmaxf(v1.z, 0.f) * w, fmaxf(v1.w, 0.f) * w);
    red_add_v4(out + lane * 4, v0);
    red_add_v4(out + (lane + 32) * 4, v1);
}

// ---------------- final: out = log_softmax(agg2[mask] @ W2 + b2) -------------
__global__ void __launch_bounds__(256) k_final(const int* __restrict__ mask,
                                               const float* __restrict__ W2,
                                               const float* __restrict__ b2,
                                               float* __restrict__ out) {
    __shared__ __align__(16) float As[RPB][DIM];
    int j = threadIdx.x;                 // output column 0..255
    int base = blockIdx.x * RPB;

    // gather RPB masked rows of agg2 into smem
#pragma unroll
    for (int r = 0; r < RPB; r++) {
        int node = __ldg(mask + base + r);
        As[r][j] = g_agg2[(size_t)node * DIM + j];
    }
    __syncthreads();

    float acc[RPB];
    float bj = __ldg(b2 + j);
#pragma unroll
    for (int r = 0; r < RPB; r++) acc[r] = bj;

    // k-loop unrolled by 4 with float4 smem broadcasts
    for (int k4 = 0; k4 < DIM / 4; k4++) {
        float w0 = __ldg(W2 + (4 * k4 + 0) * DIM + j);
        float w1 = __ldg(W2 + (4 * k4 + 1) * DIM + j);
        float w2 = __ldg(W2 + (4 * k4 + 2) * DIM + j);
        float w3 = __ldg(W2 + (4 * k4 + 3) * DIM + j);
#pragma unroll
        for (int r = 0; r < RPB; r++) {
            float4 a = reinterpret_cast<const float4*>(&As[r][0])[k4];
            acc[r] += a.x * w0;
            acc[r] += a.y * w1;
            acc[r] += a.z * w2;
            acc[r] += a.w * w3;
        }
    }
    __syncthreads();

    // stash logits back into smem for the row-wise reductions
#pragma unroll
    for (int r = 0; r < RPB; r++) As[r][j] = acc[r];
    __syncthreads();

    // 8 warps, each handles 2 rows: max, log-sum-exp, write
    int wid = j >> 5, lane = j & 31;
    for (int r = wid; r < RPB; r += 8) {
        float m = -INFINITY;
        for (int c = lane; c < DIM; c += 32) m = fmaxf(m, As[r][c]);
#pragma unroll
        for (int off = 16; off > 0; off >>= 1)
            m = fmaxf(m, __shfl_xor_sync(0xFFFFFFFFu, m, off));
        float sum = 0.f;
        for (int c = lane; c < DIM; c += 32) sum += expf(As[r][c] - m);
#pragma unroll
        for (int off = 16; off > 0; off >>= 1)
            sum += __shfl_xor_sync(0xFFFFFFFFu, sum, off);
        float lse = m + logf(sum);
        for (int c = lane; c < DIM; c += 32)
            out[(size_t)(base + r) * DIM + c] = As[r][c] - lse;
    }
}

// ---------------- launch ------------------------------------------------------
extern "C" void kernel_launch(void* const* d_in, const int* in_sizes, int n_in,
                              void* d_out, int out_size) {
    const int*   x    = (const int*)  d_in[0];          // [N_NODES,1] int32
    const int*   ei   = (const int*)  d_in[1];          // [2, N_EDGES] int32
    const int*   mask = (const int*)  d_in[2];          // [N_MASK] int32
    const float* emb  = (const float*)d_in[3];          // [256,256]
    const float* W1   = (const float*)d_in[4];          // [256,256]
    const float* b1   = (const float*)d_in[5];          // [256]
    const float* W2   = (const float*)d_in[6];          // [256,256]
    const float* b2   = (const float*)d_in[7];          // [256]
    float* out = (float*)d_out;                         // [N_MASK,256]

    const int* src = ei;
    const int* dst = ei + N_EDGES;

    // degree / dinv
    k_deg_init<<<(N_NODES + 255) / 256, 256>>>();
    k_deg_count<<<(N_EDGES + 255) / 256, 256>>>(dst);
    k_rsqrt<<<(N_NODES + 255) / 256, 256>>>();

    // EW1 = emb @ W1
    k_ew1<<<DIM, DIM>>>(emb, W1);

    // layer 1
    k_agg1_init<<<(N_NODES * 64 + 255) / 256, 256>>>(x, b1);
    k_edge1<<<(N_EDGES * 32 + 255) / 256, 256>>>(src, dst, x);

    // layer 2 (relu fused into reads)
    k_agg2_init<<<(N_NODES * 64 + 255) / 256, 256>>>();
    k_edge2<<<(N_EDGES * 32 + 255) / 256, 256>>>(src, dst);

    // masked GEMM + bias + log_softmax
    k_final<<<N_MASK / RPB, 256>>>(mask, W2, b2, out);
}

// round 4
// speedup vs baseline: 2.7234x; 2.7234x over previous
#include <cuda_runtime.h>
#include <cstdint>
#include <math.h>

#define N_NODES 100000
#define N_EDGES 800000
#define DIM     256
#define N_MASK  10000
#define RPB     16
#define SCAN_BLK 512
#define N_SCAN_BLKS ((N_NODES + SCAN_BLK - 1) / SCAN_BLK)   // 196

// ---------------- scratch (device globals) -----------------------------------
__device__ __align__(16) float g_dinv[N_NODES];
__device__ __align__(16) float g_EW1[DIM * DIM];
__device__ __align__(16) float g_agg1[(size_t)N_NODES * DIM];
__device__ __align__(16) float g_h2[(size_t)N_MASK * DIM];
__device__ int   g_cnt[N_NODES];
__device__ int   g_rowptr[N_NODES + 1];
__device__ int   g_cursor[N_NODES];
__device__ int   g_blksum[256];
__device__ int   g_blkoff[256];
__device__ int   g_csr_s[N_EDGES];
__device__ float g_csr_w[N_EDGES];

// ---------------- CSR build ---------------------------------------------------
__global__ void k_zero_cnt() {
    int i = blockIdx.x * blockDim.x + threadIdx.x;
    if (i < N_NODES) g_cnt[i] = 0;
}

__global__ void k_hist(const int* __restrict__ dst) {
    int e = blockIdx.x * blockDim.x + threadIdx.x;
    if (e < N_EDGES) atomicAdd(&g_cnt[dst[e]], 1);
}

// block-local inclusive scan -> exclusive partials + block sums; also dinv
__global__ void k_scan1() {
    __shared__ int s[SCAN_BLK];
    int t = threadIdx.x;
    int i = blockIdx.x * SCAN_BLK + t;
    int v = (i < N_NODES) ? g_cnt[i] : 0;
    if (i < N_NODES) g_dinv[i] = rsqrtf((float)v + 1.0f);   // +1 self-loop
    s[t] = v; __syncthreads();
#pragma unroll
    for (int off = 1; off < SCAN_BLK; off <<= 1) {
        int add = (t >= off) ? s[t - off] : 0;
        __syncthreads();
        s[t] += add;
        __syncthreads();
    }
    if (i < N_NODES) g_rowptr[i] = s[t] - v;
    if (t == SCAN_BLK - 1) g_blksum[blockIdx.x] = s[t];
}

__global__ void k_scan2() {   // single block of 256, scans N_SCAN_BLKS sums
    __shared__ int s[256];
    int t = threadIdx.x;
    int v = (t < N_SCAN_BLKS) ? g_blksum[t] : 0;
    s[t] = v; __syncthreads();
#pragma unroll
    for (int off = 1; off < 256; off <<= 1) {
        int add = (t >= off) ? s[t - off] : 0;
        __syncthreads();
        s[t] += add;
        __syncthreads();
    }
    g_blkoff[t] = s[t] - v;
}

__global__ void k_scan3() {
    int i = blockIdx.x * blockDim.x + threadIdx.x;
    if (i < N_NODES) {
        int rp = g_rowptr[i] + g_blkoff[i >> 9];
        g_rowptr[i] = rp;
        g_cursor[i] = rp;
    }
    if (i == 0) g_rowptr[N_NODES] = N_EDGES;
}

__global__ void k_scatter(const int* __restrict__ src, const int* __restrict__ dst) {
    int e = blockIdx.x * blockDim.x + threadIdx.x;
    if (e >= N_EDGES) return;
    int s = __ldg(src + e), d = __ldg(dst + e);
    int pos = atomicAdd(&g_cursor[d], 1);
    g_csr_s[pos] = s;
    g_csr_w[pos] = g_dinv[s] * g_dinv[d];   // full edge norm
}

// ---------------- EW1 = emb @ W1 ----------------------------------------------
__global__ void k_ew1(const float* __restrict__ emb, const float* __restrict__ W1) {
    __shared__ float es[DIM];
    int row = blockIdx.x, j = threadIdx.x;
    es[j] = emb[row * DIM + j];
    __syncthreads();
    float acc = 0.f;
#pragma unroll 16
    for (int k = 0; k < DIM; k++) acc += es[k] * __ldg(W1 + k * DIM + j);
    g_EW1[row * DIM + j] = acc;
}

// ---------------- layer 1: warp-per-node CSR gather (no atomics) --------------
__global__ void __launch_bounds__(256) k_l1_gather(const int* __restrict__ x,
                                                   const float* __restrict__ b1) {
    int warp = threadIdx.x >> 5, lane = threadIdx.x & 31;
    int node = blockIdx.x * 8 + warp;
    if (node >= N_NODES) return;

    const float4* EW = reinterpret_cast<const float4*>(g_EW1);
    float dd = g_dinv[node];
    float ws = dd * dd;                                  // self-loop weight
    int   xv = __ldg(x + node);
    float4 v0 = EW[(size_t)xv * 64 + lane];
    float4 v1 = EW[(size_t)xv * 64 + lane + 32];
    float4 bb0 = reinterpret_cast<const float4*>(b1)[lane];
    float4 bb1 = reinterpret_cast<const float4*>(b1)[lane + 32];
    float4 a0 = make_float4(bb0.x + ws * v0.x, bb0.y + ws * v0.y,
                            bb0.z + ws * v0.z, bb0.w + ws * v0.w);
    float4 a1 = make_float4(bb1.x + ws * v1.x, bb1.y + ws * v1.y,
                            bb1.z + ws * v1.z, bb1.w + ws * v1.w);

    int beg = g_rowptr[node], end = g_rowptr[node + 1];
    if (beg < end) {
        int   sc = __ldg(g_csr_s + beg);
        float wc = __ldg(g_csr_w + beg);
        int   xc = __ldg(x + sc);
        for (int k = beg; k < end; k++) {
            int sn = 0, xn = 0; float wn = 0.f;
            if (k + 1 < end) {                            // prefetch next edge
                sn = __ldg(g_csr_s + k + 1);
                wn = __ldg(g_csr_w + k + 1);
                xn = __ldg(x + sn);
            }
            const float4* r = EW + (size_t)xc * 64;
            float4 e0 = r[lane], e1 = r[lane + 32];
            a0.x += wc * e0.x; a0.y += wc * e0.y; a0.z += wc * e0.z; a0.w += wc * e0.w;
            a1.x += wc * e1.x; a1.y += wc * e1.y; a1.z += wc * e1.z; a1.w += wc * e1.w;
            sc = sn; wc = wn; xc = xn;
        }
    }
    float4* out = reinterpret_cast<float4*>(g_agg1) + (size_t)node * 64;
    out[lane] = a0;
    out[lane + 32] = a1;
}

// ---------------- layer 2: gather ONLY at masked nodes ------------------------
__global__ void __launch_bounds__(256) k_l2_gather(const int* __restrict__ mask) {
    int warp = threadIdx.x >> 5, lane = threadIdx.x & 31;
    int i = blockIdx.x * 8 + warp;
    if (i >= N_MASK) return;

    int node = __ldg(mask + i);
    const float4* A1 = reinterpret_cast<const float4*>(g_agg1);
    float dd = g_dinv[node];
    float ws = dd * dd;
    float4 v0 = A1[(size_t)node * 64 + lane];
    float4 v1 = A1[(size_t)node * 64 + lane + 32];
    float4 a0 = make_float4(ws * fmaxf(v0.x, 0.f), ws * fmaxf(v0.y, 0.f),
                            ws * fmaxf(v0.z, 0.f), ws * fmaxf(v0.w, 0.f));
    float4 a1 = make_float4(ws * fmaxf(v1.x, 0.f), ws * fmaxf(v1.y, 0.f),
                            ws * fmaxf(v1.z, 0.f), ws * fmaxf(v1.w, 0.f));

    int beg = g_rowptr[node], end = g_rowptr[node + 1];
    for (int k = beg; k < end; k++) {
        int   s = __ldg(g_csr_s + k);
        float w = __ldg(g_csr_w + k);
        float4 e0 = A1[(size_t)s * 64 + lane];
        float4 e1 = A1[(size_t)s * 64 + lane + 32];
        a0.x += w * fmaxf(e0.x, 0.f); a0.y += w * fmaxf(e0.y, 0.f);
        a0.z += w * fmaxf(e0.z, 0.f); a0.w += w * fmaxf(e0.w, 0.f);
        a1.x += w * fmaxf(e1.x, 0.f); a1.y += w * fmaxf(e1.y, 0.f);
        a1.z += w * fmaxf(e1.z, 0.f); a1.w += w * fmaxf(e1.w, 0.f);
    }
    float4* out = reinterpret_cast<float4*>(g_h2) + (size_t)i * 64;
    out[lane] = a0;
    out[lane + 32] = a1;
}

// ---------------- final: out = log_softmax(h2 @ W2 + b2) ----------------------
__global__ void __launch_bounds__(256) k_final(const float* __restrict__ W2,
                                               const float* __restrict__ b2,
                                               float* __restrict__ out) {
    __shared__ __align__(16) float As[RPB][DIM];
    int j = threadIdx.x;
    int base = blockIdx.x * RPB;

#pragma unroll
    for (int r = 0; r < RPB; r++)
        As[r][j] = g_h2[(size_t)(base + r) * DIM + j];
    __syncthreads();

    float acc[RPB];
    float bj = __ldg(b2 + j);
#pragma unroll
    for (int r = 0; r < RPB; r++) acc[r] = bj;

    for (int k4 = 0; k4 < DIM / 4; k4++) {
        float w0 = __ldg(W2 + (4 * k4 + 0) * DIM + j);
        float w1 = __ldg(W2 + (4 * k4 + 1) * DIM + j);
        float w2 = __ldg(W2 + (4 * k4 + 2) * DIM + j);
        float w3 = __ldg(W2 + (4 * k4 + 3) * DIM + j);
#pragma unroll
        for (int r = 0; r < RPB; r++) {
            float4 a = reinterpret_cast<const float4*>(&As[r][0])[k4];
            acc[r] += a.x * w0;
            acc[r] += a.y * w1;
            acc[r] += a.z * w2;
            acc[r] += a.w * w3;
        }
    }
    __syncthreads();

#pragma unroll
    for (int r = 0; r < RPB; r++) As[r][j] = acc[r];
    __syncthreads();

    int wid = j >> 5, lane = j & 31;
    for (int r = wid; r < RPB; r += 8) {
        float m = -INFINITY;
        for (int c = lane; c < DIM; c += 32) m = fmaxf(m, As[r][c]);
#pragma unroll
        for (int off = 16; off > 0; off >>= 1)
            m = fmaxf(m, __shfl_xor_sync(0xFFFFFFFFu, m, off));
        float sum = 0.f;
        for (int c = lane; c < DIM; c += 32) sum += expf(As[r][c] - m);
#pragma unroll
        for (int off = 16; off > 0; off >>= 1)
            sum += __shfl_xor_sync(0xFFFFFFFFu, sum, off);
        float lse = m + logf(sum);
        for (int c = lane; c < DIM; c += 32)
            out[(size_t)(base + r) * DIM + c] = As[r][c] - lse;
    }
}

// ---------------- launch -------------------------------------------------------
extern "C" void kernel_launch(void* const* d_in, const int* in_sizes, int n_in,
                              void* d_out, int out_size) {
    const int*   x    = (const int*)  d_in[0];
    const int*   ei   = (const int*)  d_in[1];
    const int*   mask = (const int*)  d_in[2];
    const float* emb  = (const float*)d_in[3];
    const float* W1   = (const float*)d_in[4];
    const float* b1   = (const float*)d_in[5];
    const float* W2   = (const float*)d_in[6];
    const float* b2   = (const float*)d_in[7];
    float* out = (float*)d_out;

    const int* src = ei;
    const int* dst = ei + N_EDGES;

    // CSR build (histogram -> scan -> scatter), also computes dinv
    k_zero_cnt<<<(N_NODES + 255) / 256, 256>>>();
    k_hist<<<(N_EDGES + 255) / 256, 256>>>(dst);
    k_scan1<<<N_SCAN_BLKS, SCAN_BLK>>>();
    k_scan2<<<1, 256>>>();
    k_scan3<<<(N_NODES + 255) / 256, 256>>>();
    k_scatter<<<(N_EDGES + 255) / 256, 256>>>(src, dst);

    // EW1 = emb @ W1
    k_ew1<<<DIM, DIM>>>(emb, W1);

    // layer 1: full-node CSR gather (self-loop + b1 fused)
    k_l1_gather<<<(N_NODES + 7) / 8, 256>>>(x, b1);

    // layer 2: only masked nodes (relu fused)
    k_l2_gather<<<(N_MASK + 7) / 8, 256>>>(mask);

    // masked GEMM + bias + log_softmax
    k_final<<<N_MASK / RPB, 256>>>(W2, b2, out);
}

// round 6
// speedup vs baseline: 2.7942x; 1.0260x over previous
#include <cuda_runtime.h>
#include <cstdint>
#include <math.h>

#define N_NODES 100000
#define N_EDGES 800000
#define DIM     256
#define N_MASK  10000
#define RPB     16
#define SCAN_BLK 512
#define N_SCAN_BLKS ((N_NODES + SCAN_BLK - 1) / SCAN_BLK)   // 196

// ---------------- scratch (device globals) -----------------------------------
__device__ __align__(16) float  g_dinv[N_NODES];
__device__ __align__(16) float  g_EW1[DIM * DIM];
__device__ __align__(16) float  g_agg1[(size_t)N_NODES * DIM];
__device__ __align__(16) float  g_h2[(size_t)N_MASK * DIM];
__device__ int    g_cnt[N_NODES];
__device__ int    g_rowptr[N_NODES + 1];
__device__ int    g_blksum[256];
__device__ int    g_rank[N_EDGES];
__device__ int    g_csr_s[N_EDGES];
__device__ __align__(8) float2 g_csr_xw[N_EDGES];   // {w, x[src] as float bits}

// ---------------- CSR build ---------------------------------------------------
// histogram; atomic return value = rank of edge within its dst bucket
__global__ void k_hist(const int* __restrict__ dst) {
    int e = blockIdx.x * blockDim.x + threadIdx.x;
    if (e < N_EDGES) {
        int d = __ldg(dst + e);
        g_rank[e] = atomicAdd(&g_cnt[d], 1);
    }
}

// block-local scan of counts -> partial rowptr + block sums; also dinv
__global__ void k_scan1() {
    __shared__ int s[SCAN_BLK];
    int t = threadIdx.x;
    int i = blockIdx.x * SCAN_BLK + t;
    int v = (i < N_NODES) ? g_cnt[i] : 0;
    if (i < N_NODES) g_dinv[i] = rsqrtf((float)v + 1.0f);   // +1 self-loop
    s[t] = v; __syncthreads();
#pragma unroll
    for (int off = 1; off < SCAN_BLK; off <<= 1) {
        int add = (t >= off) ? s[t - off] : 0;
        __syncthreads();
        s[t] += add;
        __syncthreads();
    }
    if (i < N_NODES) g_rowptr[i] = s[t] - v;
    if (t == SCAN_BLK - 1) g_blksum[blockIdx.x] = s[t];
}

// fused: every block redundantly scans the 196 block sums, then applies offsets
__global__ void k_scan2_apply() {
    __shared__ int s[256];
    __shared__ int ex[256];
    int t = threadIdx.x;
    int v = (t < N_SCAN_BLKS) ? g_blksum[t] : 0;
    s[t] = v; __syncthreads();
#pragma unroll
    for (int off = 1; off < 256; off <<= 1) {
        int add = (t >= off) ? s[t - off] : 0;
        __syncthreads();
        s[t] += add;
        __syncthreads();
    }
    ex[t] = s[t] - v;
    __syncthreads();
    int i = blockIdx.x * 256 + t;
    if (i < N_NODES) g_rowptr[i] += ex[i >> 9];
    if (i == 0) g_rowptr[N_NODES] = N_EDGES;
}

// scatter without atomics: pos = rowptr[dst] + rank; payload carries x[src] & w
__global__ void k_scatter(const int* __restrict__ src, const int* __restrict__ dst,
                          const int* __restrict__ x) {
    int e = blockIdx.x * blockDim.x + threadIdx.x;
    if (e >= N_EDGES) return;
    int s = __ldg(src + e), d = __ldg(dst + e);
    float w = g_dinv[s] * g_dinv[d];
    int pos = g_rowptr[d] + g_rank[e];
    g_csr_s[pos]  = s;
    g_csr_xw[pos] = make_float2(w, __int_as_float(__ldg(x + s)));
}

// ---------------- EW1 = emb @ W1, k-split x4 for occupancy --------------------
__global__ void k_ew1(const float* __restrict__ emb, const float* __restrict__ W1) {
    __shared__ float es[64];
    int row = blockIdx.x, j = threadIdx.x, kq = blockIdx.y * 64;
    if (j < 64) es[j] = __ldg(emb + row * DIM + kq + j);
    __syncthreads();
    float acc = 0.f;
#pragma unroll
    for (int k = 0; k < 64; k++) acc += es[k] * __ldg(W1 + (kq + k) * DIM + j);
    atomicAdd(&g_EW1[row * DIM + j], acc);
}

// ---------------- layer 1: warp-per-(node, half) CSR gather -------------------
__global__ void __launch_bounds__(256) k_l1_gather(const int* __restrict__ x,
                                                   const float* __restrict__ b1) {
    int warp = threadIdx.x >> 5, lane = threadIdx.x & 31;
    int node = blockIdx.x * 8 + warp;
    if (node >= N_NODES) return;
    int off = (blockIdx.y << 5) + lane;          // float4 index 0..63

    const float4* EW = reinterpret_cast<const float4*>(g_EW1);
    float dd = g_dinv[node];
    float ws = dd * dd;                          // self-loop weight
    int   xv = __ldg(x + node);
    float4 v  = EW[(size_t)xv * 64 + off];
    float4 bb = reinterpret_cast<const float4*>(b1)[off];
    float4 a0 = make_float4(bb.x + ws * v.x, bb.y + ws * v.y,
                            bb.z + ws * v.z, bb.w + ws * v.w);
    float4 a1 = make_float4(0.f, 0.f, 0.f, 0.f);

    int k = g_rowptr[node], end = g_rowptr[node + 1];
    for (; k + 1 < end; k += 2) {
        float2 xw0 = __ldg(g_csr_xw + k);
        float2 xw1 = __ldg(g_csr_xw + k + 1);
        int x0 = __float_as_int(xw0.y), x1 = __float_as_int(xw1.y);
        float4 e0 = EW[(size_t)x0 * 64 + off];
        float4 e1 = EW[(size_t)x1 * 64 + off];
        a0.x += xw0.x * e0.x; a0.y += xw0.x * e0.y;
        a0.z += xw0.x * e0.z; a0.w += xw0.x * e0.w;
        a1.x += xw1.x * e1.x; a1.y += xw1.x * e1.y;
        a1.z += xw1.x * e1.z; a1.w += xw1.x * e1.w;
    }
    if (k < end) {
        float2 xw = __ldg(g_csr_xw + k);
        int xs = __float_as_int(xw.y);
        float4 e = EW[(size_t)xs * 64 + off];
        a0.x += xw.x * e.x; a0.y += xw.x * e.y;
        a0.z += xw.x * e.z; a0.w += xw.x * e.w;
    }
    a0.x += a1.x; a0.y += a1.y; a0.z += a1.z; a0.w += a1.w;
    reinterpret_cast<float4*>(g_agg1)[(size_t)node * 64 + off] = a0;
}

// ---------------- layer 2: only masked nodes, warp-per-(row, half) ------------
__global__ void __launch_bounds__(256) k_l2_gather(const int* __restrict__ mask) {
    int warp = threadIdx.x >> 5, lane = threadIdx.x & 31;
    int i = blockIdx.x * 8 + warp;
    if (i >= N_MASK) return;
    int off = (blockIdx.y << 5) + lane;

    int node = __ldg(mask + i);
    const float4* A1 = reinterpret_cast<const float4*>(g_agg1);
    float dd = g_dinv[node];
    float ws = dd * dd;
    float4 v = A1[(size_t)node * 64 + off];
    float4 a0 = make_float4(ws * fmaxf(v.x, 0.f), ws * fmaxf(v.y, 0.f),
                            ws * fmaxf(v.z, 0.f), ws * fmaxf(v.w, 0.f));
    float4 a1 = make_float4(0.f, 0.f, 0.f, 0.f);

    int k = g_rowptr[node], end = g_rowptr[node + 1];
    for (; k + 1 < end; k += 2) {
        int   s0 = __ldg(g_csr_s + k);
        int   s1 = __ldg(g_csr_s + k + 1);
        float w0 = __ldg(&g_csr_xw[k].x);
        float w1 = __ldg(&g_csr_xw[k + 1].x);
        float4 e0 = A1[(size_t)s0 * 64 + off];
        float4 e1 = A1[(size_t)s1 * 64 + off];
        a0.x += w0 * fmaxf(e0.x, 0.f); a0.y += w0 * fmaxf(e0.y, 0.f);
        a0.z += w0 * fmaxf(e0.z, 0.f); a0.w += w0 * fmaxf(e0.w, 0.f);
        a1.x += w1 * fmaxf(e1.x, 0.f); a1.y += w1 * fmaxf(e1.y, 0.f);
        a1.z += w1 * fmaxf(e1.z, 0.f); a1.w += w1 * fmaxf(e1.w, 0.f);
    }
    if (k < end) {
        int   s = __ldg(g_csr_s + k);
        float w = __ldg(&g_csr_xw[k].x);
        float4 e = A1[(size_t)s * 64 + off];
        a0.x += w * fmaxf(e.x, 0.f); a0.y += w * fmaxf(e.y, 0.f);
        a0.z += w * fmaxf(e.z, 0.f); a0.w += w * fmaxf(e.w, 0.f);
    }
    a0.x += a1.x; a0.y += a1.y; a0.z += a1.z; a0.w += a1.w;
    reinterpret_cast<float4*>(g_h2)[(size_t)i * 64 + off] = a0;
}

// ---------------- final: out = log_softmax(h2 @ W2 + b2) ----------------------
__global__ void __launch_bounds__(256) k_final(const float* __restrict__ W2,
                                               const float* __restrict__ b2,
                                               float* __restrict__ out) {
    __shared__ __align__(16) float As[RPB][DIM];
    int j = threadIdx.x;
    int base = blockIdx.x * RPB;

#pragma unroll
    for (int r = 0; r < RPB; r++)
        As[r][j] = g_h2[(size_t)(base + r) * DIM + j];
    __syncthreads();

    float acc[RPB];
    float bj = __ldg(b2 + j);
#pragma unroll
    for (int r = 0; r < RPB; r++) acc[r] = bj;

    for (int k4 = 0; k4 < DIM / 4; k4++) {
        float w0 = __ldg(W2 + (4 * k4 + 0) * DIM + j);
        float w1 = __ldg(W2 + (4 * k4 + 1) * DIM + j);
        float w2 = __ldg(W2 + (4 * k4 + 2) * DIM + j);
        float w3 = __ldg(W2 + (4 * k4 + 3) * DIM + j);
#pragma unroll
        for (int r = 0; r < RPB; r++) {
            float4 a = reinterpret_cast<const float4*>(&As[r][0])[k4];
            acc[r] += a.x * w0;
            acc[r] += a.y * w1;
            acc[r] += a.z * w2;
            acc[r] += a.w * w3;
        }
    }
    __syncthreads();

#pragma unroll
    for (int r = 0; r < RPB; r++) As[r][j] = acc[r];
    __syncthreads();

    int wid = j >> 5, lane = j & 31;
    for (int r = wid; r < RPB; r += 8) {
        float m = -INFINITY;
        for (int c = lane; c < DIM; c += 32) m = fmaxf(m, As[r][c]);
#pragma unroll
        for (int off = 16; off > 0; off >>= 1)
            m = fmaxf(m, __shfl_xor_sync(0xFFFFFFFFu, m, off));
        float sum = 0.f;
        for (int c = lane; c < DIM; c += 32) sum += expf(As[r][c] - m);
#pragma unroll
        for (int off = 16; off > 0; off >>= 1)
            sum += __shfl_xor_sync(0xFFFFFFFFu, sum, off);
        float lse = m + logf(sum);
        for (int c = lane; c < DIM; c += 32)
            out[(size_t)(base + r) * DIM + c] = As[r][c] - lse;
    }
}

// ---------------- launch -------------------------------------------------------
extern "C" void kernel_launch(void* const* d_in, const int* in_sizes, int n_in,
                              void* d_out, int out_size) {
    const int*   x    = (const int*)  d_in[0];
    const int*   ei   = (const int*)  d_in[1];
    const int*   mask = (const int*)  d_in[2];
    const float* emb  = (const float*)d_in[3];
    const float* W1   = (const float*)d_in[4];
    const float* b1   = (const float*)d_in[5];
    const float* W2   = (const float*)d_in[6];
    const float* b2   = (const float*)d_in[7];
    float* out = (float*)d_out;

    const int* src = ei;
    const int* dst = ei + N_EDGES;

    void *p_cnt = nullptr, *p_ew1 = nullptr;
    cudaGetSymbolAddress(&p_cnt, g_cnt);
    cudaGetSymbolAddress(&p_ew1, g_EW1);
    cudaMemsetAsync(p_cnt, 0, N_NODES * sizeof(int));
    cudaMemsetAsync(p_ew1, 0, DIM * DIM * sizeof(float));

    // CSR build
    k_hist<<<(N_EDGES + 255) / 256, 256>>>(dst);
    k_scan1<<<N_SCAN_BLKS, SCAN_BLK>>>();
    k_scan2_apply<<<(N_NODES + 255) / 256, 256>>>();
    k_scatter<<<(N_EDGES + 255) / 256, 256>>>(src, dst, x);

    // EW1 = emb @ W1 (k-split x4)
    {
        dim3 g(DIM, 4);
        k_ew1<<<g, DIM>>>(emb, W1);
    }

    // layer 1: full-node CSR gather (self-loop + b1 fused), feature-split x2
    {
        dim3 g((N_NODES + 7) / 8, 2);
        k_l1_gather<<<g, 256>>>(x, b1);
    }

    // layer 2: only masked nodes (relu fused), feature-split x2
    {
        dim3 g((N_MASK + 7) / 8, 2);
        k_l2_gather<<<g, 256>>>(mask);
    }

    // masked GEMM + bias + log_softmax
    k_final<<<N_MASK / RPB, 256>>>(W2, b2, out);
}